// round 1
// baseline (speedup 1.0000x reference)
#include <cuda_runtime.h>

#define NL 2
#define NH 8
#define SEQ 1024
#define HIDX 512
#define HH 4096
#define NE 8
#define FFN 1024
#define NB 4
#define TOK 4096
#define EPSV 1e-5f
#define MAXROWS 4608
#define MAXT 72

static __device__ float g_q[(size_t)NB * SEQ * HH];
static __device__ float g_k[(size_t)NB * SEQ * HH];
static __device__ float g_v[(size_t)NB * SEQ * HH];
static __device__ float g_sc[(size_t)NB * NH * SEQ * SEQ];
static __device__ float g_o2[(size_t)NB * SEQ * HH];
static __device__ float g_t1[(size_t)TOK * HIDX];
static __device__ float g_x[(size_t)TOK * HIDX];
static __device__ float g_y[(size_t)TOK * HIDX];
static __device__ float g_h[(size_t)MAXROWS * FFN];
static __device__ int   g_sel[TOK];
static __device__ float g_wsel[TOK];
static __device__ int   g_perm[MAXROWS];
static __device__ int   g_texp[MAXT];

// ---------------------------------------------------------------------------
// Generic batched SGEMM: C = A @ B (+bias), 128x64x16 tiles, 8x4 per thread.
// Batch offset = (z>>3)*Sb + (z&7)*Sh  (covers the [B,H] batching pattern).
// transB: B stored [N,K] row-major (scores NT case).
// causalSkip: skip tiles entirely above the diagonal (masked scores).
// causalK: truncate K-loop at row0+128 (masked AV: attn[i,j]=0 for j>i).
// ---------------------------------------------------------------------------
__global__ void __launch_bounds__(256) gemm_kernel(
    const float* __restrict__ A, int lda, long long aSb, long long aSh,
    const float* __restrict__ B, int ldb, long long bSb, long long bSh,
    float* __restrict__ C, int ldc, long long cSb, long long cSh,
    const float* __restrict__ bias,
    int K, int transB, int causalSkip, int causalK)
{
    int row0 = blockIdx.y * 128;
    int col0 = blockIdx.x * 64;
    if (causalSkip && col0 >= row0 + 128) return;
    int z = blockIdx.z;
    A += (long long)(z >> 3) * aSb + (long long)(z & 7) * aSh;
    B += (long long)(z >> 3) * bSb + (long long)(z & 7) * bSh;
    C += (long long)(z >> 3) * cSb + (long long)(z & 7) * cSh;

    __shared__ float As[16][132];
    __shared__ float Bs[16][68];
    int tid = threadIdx.x;
    int tx = tid & 15, ty = tid >> 4;
    float acc[8][4];
#pragma unroll
    for (int i = 0; i < 8; i++)
#pragma unroll
        for (int j = 0; j < 4; j++) acc[i][j] = 0.f;

    int kend = causalK ? (row0 + 128) : K;
    for (int k0 = 0; k0 < kend; k0 += 16) {
        // A tile: 128x16, float4 per load, 2 per thread
#pragma unroll
        for (int t = 0; t < 2; t++) {
            int idx = tid + t * 256;
            int mm = idx >> 2;
            int k4 = (idx & 3) << 2;
            float4 va = *(const float4*)(A + (long long)(row0 + mm) * lda + k0 + k4);
            As[k4 + 0][mm] = va.x; As[k4 + 1][mm] = va.y;
            As[k4 + 2][mm] = va.z; As[k4 + 3][mm] = va.w;
        }
        if (!transB) {
            int kk = tid >> 4;
            int nn = (tid & 15) << 2;
            float4 vb = *(const float4*)(B + (long long)(k0 + kk) * ldb + col0 + nn);
            Bs[kk][nn] = vb.x; Bs[kk][nn + 1] = vb.y;
            Bs[kk][nn + 2] = vb.z; Bs[kk][nn + 3] = vb.w;
        } else {
            int nn = tid >> 2;
            int k4 = (tid & 3) << 2;
            float4 vb = *(const float4*)(B + (long long)(col0 + nn) * ldb + k0 + k4);
            Bs[k4 + 0][nn] = vb.x; Bs[k4 + 1][nn] = vb.y;
            Bs[k4 + 2][nn] = vb.z; Bs[k4 + 3][nn] = vb.w;
        }
        __syncthreads();
#pragma unroll
        for (int kk = 0; kk < 16; kk++) {
            float av[8], bv[4];
#pragma unroll
            for (int i = 0; i < 8; i++) av[i] = As[kk][ty * 8 + i];
#pragma unroll
            for (int j = 0; j < 4; j++) bv[j] = Bs[kk][tx * 4 + j];
#pragma unroll
            for (int i = 0; i < 8; i++)
#pragma unroll
                for (int j = 0; j < 4; j++)
                    acc[i][j] = fmaf(av[i], bv[j], acc[i][j]);
        }
        __syncthreads();
    }
#pragma unroll
    for (int i = 0; i < 8; i++) {
        long long r = row0 + ty * 8 + i;
#pragma unroll
        for (int j = 0; j < 4; j++) {
            int c = col0 + tx * 4 + j;
            float vv = acc[i][j];
            if (bias) vv += bias[c];
            C[r * ldc + c] = vv;
        }
    }
}

// ---------------------------------------------------------------------------
// Softmax over rows of length SEQ. masked: row i uses only the first i+1
// elements; masked positions are written as 0 (never read from input).
// ---------------------------------------------------------------------------
__global__ void __launch_bounds__(256) softmax_kernel(float* __restrict__ sc, int masked)
{
    long long base = (long long)blockIdx.x * SEQ;
    int i = blockIdx.x & (SEQ - 1);
    int n = masked ? (i + 1) : SEQ;
    int tid = threadIdx.x;
    __shared__ float red[8];

    float v[4];
    float mx = -1e30f;
#pragma unroll
    for (int j = 0; j < 4; j++) {
        int c = tid + (j << 8);
        v[j] = (c < n) ? sc[base + c] : -1e30f;
        mx = fmaxf(mx, v[j]);
    }
#pragma unroll
    for (int o = 16; o; o >>= 1) mx = fmaxf(mx, __shfl_xor_sync(0xffffffffu, mx, o));
    if ((tid & 31) == 0) red[tid >> 5] = mx;
    __syncthreads();
    mx = red[0];
#pragma unroll
    for (int w = 1; w < 8; w++) mx = fmaxf(mx, red[w]);
    __syncthreads();

    float s = 0.f;
#pragma unroll
    for (int j = 0; j < 4; j++) {
        int c = tid + (j << 8);
        v[j] = (c < n) ? __expf(v[j] - mx) : 0.f;
        s += v[j];
    }
#pragma unroll
    for (int o = 16; o; o >>= 1) s += __shfl_xor_sync(0xffffffffu, s, o);
    if ((tid & 31) == 0) red[tid >> 5] = s;
    __syncthreads();
    s = 0.f;
#pragma unroll
    for (int w = 0; w < 8; w++) s += red[w];
    float inv = 1.f / s;
#pragma unroll
    for (int j = 0; j < 4; j++) {
        int c = tid + (j << 8);
        sc[base + c] = v[j] * inv;
    }
}

// ---------------------------------------------------------------------------
// y = LayerNorm(a + r) with gain g / bias b. One block (256 thr) per row of 512.
// Safe for y == r (reads complete before reduction syncs; writes after).
// ---------------------------------------------------------------------------
__global__ void __launch_bounds__(256) ln_kernel(
    const float* __restrict__ a, const float* __restrict__ r,
    const float* __restrict__ g, const float* __restrict__ b,
    float* __restrict__ y)
{
    long long base = (long long)blockIdx.x * HIDX;
    int tid = threadIdx.x;
    __shared__ float red[8];

    float z0 = a[base + tid] + r[base + tid];
    float z1 = a[base + tid + 256] + r[base + tid + 256];
    float s = z0 + z1;
#pragma unroll
    for (int o = 16; o; o >>= 1) s += __shfl_xor_sync(0xffffffffu, s, o);
    if ((tid & 31) == 0) red[tid >> 5] = s;
    __syncthreads();
    s = 0.f;
#pragma unroll
    for (int w = 0; w < 8; w++) s += red[w];
    float m = s * (1.f / HIDX);
    float d0 = z0 - m, d1 = z1 - m;
    float qs = d0 * d0 + d1 * d1;
    __syncthreads();
#pragma unroll
    for (int o = 16; o; o >>= 1) qs += __shfl_xor_sync(0xffffffffu, qs, o);
    if ((tid & 31) == 0) red[tid >> 5] = qs;
    __syncthreads();
    qs = 0.f;
#pragma unroll
    for (int w = 0; w < 8; w++) qs += red[w];
    float inv = rsqrtf(qs * (1.f / HIDX) + EPSV);
    y[base + tid]       = g[tid] * d0 * inv + b[tid];
    y[base + tid + 256] = g[tid + 256] * d1 * inv + b[tid + 256];
}

// ---------------------------------------------------------------------------
// Gate: softmax(x@gw+gb) over E=8, pick 2nd-largest (faithful TOPK-1 bug),
// weight = p2/(p1+p2). One warp per token. Tie rule matches jax top_k
// (first occurrence wins for top1, next occurrence becomes top2).
// ---------------------------------------------------------------------------
__global__ void __launch_bounds__(256) gate_kernel(
    const float* __restrict__ x, const float* __restrict__ gw, const float* __restrict__ gb)
{
    int tok = (blockIdx.x << 3) + (threadIdx.x >> 5);
    int lane = threadIdx.x & 31;
    const float* xr = x + (size_t)tok * HIDX;
    float acc[8] = {0, 0, 0, 0, 0, 0, 0, 0};
    for (int j = lane; j < HIDX; j += 32) {
        float xv = xr[j];
        float4 a0 = *(const float4*)(gw + j * 8);
        float4 a1 = *(const float4*)(gw + j * 8 + 4);
        acc[0] += xv * a0.x; acc[1] += xv * a0.y; acc[2] += xv * a0.z; acc[3] += xv * a0.w;
        acc[4] += xv * a1.x; acc[5] += xv * a1.y; acc[6] += xv * a1.z; acc[7] += xv * a1.w;
    }
#pragma unroll
    for (int e = 0; e < 8; e++)
#pragma unroll
        for (int o = 16; o; o >>= 1) acc[e] += __shfl_xor_sync(0xffffffffu, acc[e], o);
    if (lane == 0) {
        float mx = -1e30f;
#pragma unroll
        for (int e = 0; e < 8; e++) { acc[e] += gb[e]; mx = fmaxf(mx, acc[e]); }
        float p[8];
#pragma unroll
        for (int e = 0; e < 8; e++) p[e] = __expf(acc[e] - mx);
        float v1 = -1.f, v2 = -1.f; int i1 = 0, i2 = 0;
#pragma unroll
        for (int e = 0; e < 8; e++) {
            if (p[e] > v1)      { v2 = v1; i2 = i1; v1 = p[e]; i1 = e; }
            else if (p[e] > v2) { v2 = p[e]; i2 = e; }
        }
        g_sel[tok] = i2;
        g_wsel[tok] = v2 / (v1 + v2);
    }
}

// ---------------------------------------------------------------------------
// Build tile-aligned per-expert permutation + tile descriptors (1 block).
// ---------------------------------------------------------------------------
__global__ void __launch_bounds__(256) moe_setup()
{
    __shared__ int cnt[8], cursor[8];
    int tid = threadIdx.x;
    if (tid < 8) cnt[tid] = 0;
    for (int i = tid; i < MAXROWS; i += 256) g_perm[i] = -1;
    __syncthreads();
    for (int i = tid; i < TOK; i += 256) atomicAdd(&cnt[g_sel[i]], 1);
    __syncthreads();
    if (tid == 0) {
        int base = 0, t = 0;
        for (int e = 0; e < 8; e++) {
            cursor[e] = base;
            int tiles = (cnt[e] + 63) >> 6;
            for (int j = 0; j < tiles; j++) g_texp[t++] = e;
            base += tiles << 6;
        }
        for (; t < MAXT; t++) g_texp[t] = -1;
    }
    __syncthreads();
    for (int i = tid; i < TOK; i += 256) {
        int e = g_sel[i];
        int p = atomicAdd(&cursor[e], 1);
        g_perm[p] = i;
    }
}

// ---------------------------------------------------------------------------
// MoE GEMM1: h = relu(x[perm] @ w1[e] + b1[e]), 64x64x16 tiles, 4x4/thread.
// ---------------------------------------------------------------------------
__global__ void __launch_bounds__(256) moe_gemm1(
    const float* __restrict__ x, const float* __restrict__ w1, const float* __restrict__ b1)
{
    int t = blockIdx.y;
    int e = g_texp[t];
    if (e < 0) return;
    const float* B = w1 + (size_t)e * HIDX * FFN;
    const float* bias = b1 + (size_t)e * FFN;
    int col0 = blockIdx.x << 6;
    __shared__ float As[16][68];
    __shared__ float Bs[16][68];
    __shared__ int rows[64];
    int tid = threadIdx.x;
    if (tid < 64) rows[tid] = g_perm[(t << 6) + tid];
    __syncthreads();
    int tx = tid & 15, ty = tid >> 4;
    float acc[4][4] = {};
    for (int k0 = 0; k0 < HIDX; k0 += 16) {
        int mm = tid >> 2, k4 = (tid & 3) << 2;
        int r = rows[mm];
        float4 va = make_float4(0.f, 0.f, 0.f, 0.f);
        if (r >= 0) va = *(const float4*)(x + (size_t)r * HIDX + k0 + k4);
        As[k4 + 0][mm] = va.x; As[k4 + 1][mm] = va.y;
        As[k4 + 2][mm] = va.z; As[k4 + 3][mm] = va.w;
        int kk = tid >> 4, nn = (tid & 15) << 2;
        float4 vb = *(const float4*)(B + (size_t)(k0 + kk) * FFN + col0 + nn);
        Bs[kk][nn] = vb.x; Bs[kk][nn + 1] = vb.y;
        Bs[kk][nn + 2] = vb.z; Bs[kk][nn + 3] = vb.w;
        __syncthreads();
#pragma unroll
        for (int kk2 = 0; kk2 < 16; kk2++) {
            float av[4], bv[4];
#pragma unroll
            for (int i = 0; i < 4; i++) av[i] = As[kk2][ty * 4 + i];
#pragma unroll
            for (int j = 0; j < 4; j++) bv[j] = Bs[kk2][tx * 4 + j];
#pragma unroll
            for (int i = 0; i < 4; i++)
#pragma unroll
                for (int j = 0; j < 4; j++)
                    acc[i][j] = fmaf(av[i], bv[j], acc[i][j]);
        }
        __syncthreads();
    }
#pragma unroll
    for (int i = 0; i < 4; i++) {
#pragma unroll
        for (int j = 0; j < 4; j++) {
            int c = col0 + tx * 4 + j;
            float vv = acc[i][j] + bias[c];
            vv = fmaxf(vv, 0.f);
            g_h[(size_t)((t << 6) + ty * 4 + i) * FFN + c] = vv;
        }
    }
}

// ---------------------------------------------------------------------------
// MoE GEMM2: y[tok] = (h @ w2[e] + b2[e]) * wsel[tok], scattered by perm.
// ---------------------------------------------------------------------------
__global__ void __launch_bounds__(256) moe_gemm2(
    const float* __restrict__ w2, const float* __restrict__ b2)
{
    int t = blockIdx.y;
    int e = g_texp[t];
    if (e < 0) return;
    const float* B = w2 + (size_t)e * FFN * HIDX;
    const float* bias = b2 + (size_t)e * HIDX;
    int col0 = blockIdx.x << 6;
    __shared__ float As[16][68];
    __shared__ float Bs[16][68];
    __shared__ int rows[64];
    int tid = threadIdx.x;
    if (tid < 64) rows[tid] = g_perm[(t << 6) + tid];
    __syncthreads();
    int tx = tid & 15, ty = tid >> 4;
    float acc[4][4] = {};
    for (int k0 = 0; k0 < FFN; k0 += 16) {
        int mm = tid >> 2, k4 = (tid & 3) << 2;
        float4 va = *(const float4*)(&g_h[(size_t)((t << 6) + mm) * FFN + k0 + k4]);
        As[k4 + 0][mm] = va.x; As[k4 + 1][mm] = va.y;
        As[k4 + 2][mm] = va.z; As[k4 + 3][mm] = va.w;
        int kk = tid >> 4, nn = (tid & 15) << 2;
        float4 vb = *(const float4*)(B + (size_t)(k0 + kk) * HIDX + col0 + nn);
        Bs[kk][nn] = vb.x; Bs[kk][nn + 1] = vb.y;
        Bs[kk][nn + 2] = vb.z; Bs[kk][nn + 3] = vb.w;
        __syncthreads();
#pragma unroll
        for (int kk2 = 0; kk2 < 16; kk2++) {
            float av[4], bv[4];
#pragma unroll
            for (int i = 0; i < 4; i++) av[i] = As[kk2][ty * 4 + i];
#pragma unroll
            for (int j = 0; j < 4; j++) bv[j] = Bs[kk2][tx * 4 + j];
#pragma unroll
            for (int i = 0; i < 4; i++)
#pragma unroll
                for (int j = 0; j < 4; j++)
                    acc[i][j] = fmaf(av[i], bv[j], acc[i][j]);
        }
        __syncthreads();
    }
#pragma unroll
    for (int i = 0; i < 4; i++) {
        int r = rows[ty * 4 + i];
        if (r < 0) continue;
        float ws = g_wsel[r];
#pragma unroll
        for (int j = 0; j < 4; j++) {
            int c = col0 + tx * 4 + j;
            g_y[(size_t)r * HIDX + c] = (acc[i][j] + bias[c]) * ws;
        }
    }
}

__global__ void __launch_bounds__(256) copy_kernel(float* __restrict__ dst,
                                                   const float* __restrict__ src, int n)
{
    int i = blockIdx.x * 256 + threadIdx.x;
    if (i < n) dst[i] = src[i];
}

// ---------------------------------------------------------------------------
extern "C" void kernel_launch(void* const* d_in, const int* in_sizes, int n_in,
                              void* d_out, int out_size)
{
    const float* x_in = (const float*)d_in[0];
    const float* enc  = (const float*)d_in[1];
    const float* wq = (const float*)d_in[2];
    const float* bq = (const float*)d_in[3];
    const float* wk = (const float*)d_in[4];
    const float* bk = (const float*)d_in[5];
    const float* wv = (const float*)d_in[6];
    const float* bv = (const float*)d_in[7];
    const float* wo = (const float*)d_in[8];
    const float* bo = (const float*)d_in[9];
    const float* gw = (const float*)d_in[10];
    const float* gb = (const float*)d_in[11];
    const float* w1 = (const float*)d_in[12];
    const float* b1 = (const float*)d_in[13];
    const float* w2 = (const float*)d_in[14];
    const float* b2 = (const float*)d_in[15];
    const float* lng = (const float*)d_in[16];
    const float* lnb = (const float*)d_in[17];
    float* out = (float*)d_out;

    float *q, *k, *v, *sc, *o2, *t1, *xb, *yb;
    cudaGetSymbolAddress((void**)&q,  g_q);
    cudaGetSymbolAddress((void**)&k,  g_k);
    cudaGetSymbolAddress((void**)&v,  g_v);
    cudaGetSymbolAddress((void**)&sc, g_sc);
    cudaGetSymbolAddress((void**)&o2, g_o2);
    cudaGetSymbolAddress((void**)&t1, g_t1);
    cudaGetSymbolAddress((void**)&xb, g_x);
    cudaGetSymbolAddress((void**)&yb, g_y);

    copy_kernel<<<TOK * HIDX / 256, 256>>>(xb, x_in, TOK * HIDX);

    for (int l = 0; l < NL; l++) {
        for (int a = 0; a < 2; a++) {
            const float* qin = a ? enc : xb;   // cross-attn: Q,K from encoder
            const float* kin = qin;
            const float* vin = xb;             // V always from current x (faithful)
            size_t wOff = (size_t)(l * 2 + a) * HIDX * HH;
            int msk = (a == 0);

            dim3 gProj(HH / 64, TOK / 128, 1);
            gemm_kernel<<<gProj, 256>>>(qin, HIDX, 0, 0, wq + wOff, HH, 0, 0,
                                        q, HH, 0, 0, bq + (size_t)(l * 2 + a) * HH,
                                        HIDX, 0, 0, 0);
            gemm_kernel<<<gProj, 256>>>(kin, HIDX, 0, 0, wk + wOff, HH, 0, 0,
                                        k, HH, 0, 0, bk + (size_t)(l * 2 + a) * HH,
                                        HIDX, 0, 0, 0);
            gemm_kernel<<<gProj, 256>>>(vin, HIDX, 0, 0, wv + wOff, HH, 0, 0,
                                        v, HH, 0, 0, bv + (size_t)(l * 2 + a) * HH,
                                        HIDX, 0, 0, 0);
            // scores = Q @ K^T per (b,h): NT, batch 32
            gemm_kernel<<<dim3(SEQ / 64, SEQ / 128, 32), 256>>>(
                q, HIDX, 4194304LL, 524288LL,
                k, HIDX, 4194304LL, 524288LL,
                sc, SEQ, 8388608LL, 1048576LL,
                nullptr, HIDX, 1, msk, 0);
            softmax_kernel<<<NB * NH * SEQ, 256>>>(sc, msk);
            // O2[b, s, h*512+d] = sum_j attn[b,h,s,j] * v[b,h,j,d]
            gemm_kernel<<<dim3(HIDX / 64, SEQ / 128, 32), 256>>>(
                sc, SEQ, 8388608LL, 1048576LL,
                v, HIDX, 4194304LL, 524288LL,
                o2, HH, 4194304LL, 512LL,
                nullptr, SEQ, 0, 0, msk);
            gemm_kernel<<<dim3(HIDX / 64, TOK / 128, 1), 256>>>(
                o2, HH, 0, 0, wo + wOff, HIDX, 0, 0,
                t1, HIDX, 0, 0, bo + (size_t)(l * 2 + a) * HIDX,
                HH, 0, 0, 0);
            ln_kernel<<<TOK, 256>>>(t1, xb, lng + (size_t)(l * 3 + a) * HIDX,
                                    lnb + (size_t)(l * 3 + a) * HIDX, xb);
        }
        gate_kernel<<<TOK / 8, 256>>>(xb, gw + (size_t)l * HIDX * NE, gb + (size_t)l * NE);
        moe_setup<<<1, 256>>>();
        moe_gemm1<<<dim3(FFN / 64, MAXT), 256>>>(xb, w1 + (size_t)l * NE * HIDX * FFN,
                                                 b1 + (size_t)l * NE * FFN);
        moe_gemm2<<<dim3(HIDX / 64, MAXT), 256>>>(w2 + (size_t)l * NE * FFN * HIDX,
                                                  b2 + (size_t)l * NE * HIDX);
        ln_kernel<<<TOK, 256>>>(yb, xb, lng + (size_t)(l * 3 + 2) * HIDX,
                                lnb + (size_t)(l * 3 + 2) * HIDX, xb);
    }
    copy_kernel<<<TOK * HIDX / 256, 256>>>(out, xb, TOK * HIDX);
}

// round 3
// speedup vs baseline: 1.5944x; 1.5944x over previous
#include <cuda_runtime.h>
#include <cuda_bf16.h>
#include <cstdint>

#define NL 2
#define NH 8
#define SEQ 1024
#define HIDX 512
#define HH 4096
#define NE 8
#define FFN 1024
#define NB 4
#define TOK 4096
#define EPSV 1e-5f
#define MAXROWS 4608
#define MAXT 72

static __device__ float g_q[(size_t)NB * SEQ * HH];
static __device__ float g_k[(size_t)NB * SEQ * HH];
static __device__ float g_v[(size_t)NB * SEQ * HH];
static __device__ float g_sc[(size_t)NB * NH * SEQ * SEQ];
static __device__ float g_o2[(size_t)NB * SEQ * HH];
static __device__ float g_t1[(size_t)TOK * HIDX];
static __device__ float g_x[(size_t)TOK * HIDX];
static __device__ float g_y[(size_t)TOK * HIDX];
static __device__ float g_h[(size_t)MAXROWS * FFN];
static __device__ int   g_sel[TOK];
static __device__ float g_wsel[TOK];
static __device__ int   g_perm[MAXROWS];
static __device__ int   g_texp[MAXT];

// Split a pair of floats into packed bf16x2 (hi) and packed bf16x2 residual (lo).
// pack order: low half = first element (k), high half = second element (k+1).
__device__ __forceinline__ void split2(float x, float y, uint32_t& hi, uint32_t& lo)
{
    __nv_bfloat162 h = __floats2bfloat162_rn(x, y);
    float2 hf = __bfloat1622float2(h);
    __nv_bfloat162 l = __floats2bfloat162_rn(x - hf.x, y - hf.y);
    hi = *(uint32_t*)&h;
    lo = *(uint32_t*)&l;
}

#define MMA_BF16(d, a, b)                                                     \
    asm volatile(                                                             \
        "mma.sync.aligned.m16n8k16.row.col.f32.bf16.bf16.f32 "                \
        "{%0,%1,%2,%3},{%4,%5,%6,%7},{%8,%9},{%0,%1,%2,%3};"                  \
        : "+f"(d[0]), "+f"(d[1]), "+f"(d[2]), "+f"(d[3])                      \
        : "r"(a[0]), "r"(a[1]), "r"(a[2]), "r"(a[3]), "r"(b[0]), "r"(b[1]))

// ---------------------------------------------------------------------------
// Batched split-bf16 tensor-core GEMM (fp32-accurate to ~2^-18):
// C = A @ B (+bias). 128x64 block tile, BK=16. 8 warps as 4(M)x2(N) grid of
// 32x32 warp tiles; each warp 2x4 m16n8k16 MMA tiles x 3 split terms.
// Batch offset = (z>>3)*Sb + (z&7)*Sh.
// transB: B stored [N,K] row-major (scores NT case).
// causalSkip: skip tiles entirely above diagonal. causalK: K-loop to row0+128.
// ---------------------------------------------------------------------------
__global__ void __launch_bounds__(256) gemm_kernel(
    const float* __restrict__ A, int lda, long long aSb, long long aSh,
    const float* __restrict__ B, int ldb, long long bSb, long long bSh,
    float* __restrict__ C, int ldc, long long cSb, long long cSh,
    const float* __restrict__ bias,
    int K, int transB, int causalSkip, int causalK)
{
    int row0 = blockIdx.y * 128;
    int col0 = blockIdx.x * 64;
    if (causalSkip && col0 >= row0 + 128) return;
    int z = blockIdx.z;
    A += (long long)(z >> 3) * aSb + (long long)(z & 7) * aSh;
    B += (long long)(z >> 3) * bSb + (long long)(z & 7) * bSh;
    C += (long long)(z >> 3) * cSb + (long long)(z & 7) * cSh;

    // k-pair packed tiles: As[m][kp] (kp = k/2), Bs[kp][n]
    __shared__ uint32_t AsH[128][12];  // stride 12 -> conflict-free frag reads
    __shared__ uint32_t AsL[128][12];
    __shared__ uint32_t BsH[8][72];    // stride 72 -> conflict-free frag reads
    __shared__ uint32_t BsL[8][72];

    int tid = threadIdx.x;
    int warp = tid >> 5, lane = tid & 31;
    int wm0 = (warp >> 1) << 5;   // warp M origin 0/32/64/96
    int wn0 = (warp & 1) << 5;    // warp N origin 0/32
    int tg = lane & 3, gp = lane >> 2;

    float acc[2][4][4];
#pragma unroll
    for (int i = 0; i < 2; i++)
#pragma unroll
        for (int j = 0; j < 4; j++)
#pragma unroll
            for (int t = 0; t < 4; t++) acc[i][j][t] = 0.f;

    int kend = causalK ? (row0 + 128) : K;
    for (int k0 = 0; k0 < kend; k0 += 16) {
        // ---- A tile: 128x16 floats, 2 float4 per thread ----
#pragma unroll
        for (int t = 0; t < 2; t++) {
            int idx = tid + t * 256;
            int mm = idx >> 2;
            int k4 = (idx & 3) << 2;      // k offset 0/4/8/12
            float4 va = *(const float4*)(A + (long long)(row0 + mm) * lda + k0 + k4);
            int kp = k4 >> 1;
            split2(va.x, va.y, AsH[mm][kp],     AsL[mm][kp]);
            split2(va.z, va.w, AsH[mm][kp + 1], AsL[mm][kp + 1]);
        }
        // ---- B tile: 16x64 ----
        if (!transB) {
            // pairs along k: thread loads float2 from rows 2kp, 2kp+1
            int nn2 = (tid & 31) << 1;
            int kp = tid >> 5;            // 0..7
            const float* bp = B + (long long)(k0 + (kp << 1)) * ldb + col0 + nn2;
            float2 b0 = *(const float2*)(bp);
            float2 b1 = *(const float2*)(bp + ldb);
            split2(b0.x, b1.x, BsH[kp][nn2],     BsL[kp][nn2]);
            split2(b0.y, b1.y, BsH[kp][nn2 + 1], BsL[kp][nn2 + 1]);
        } else {
            // B [N,K] row-major: float4 along k gives pairs directly
            int nn = tid >> 2;
            int k4 = (tid & 3) << 2;
            float4 vb = *(const float4*)(B + (long long)(col0 + nn) * ldb + k0 + k4);
            int kp = k4 >> 1;
            split2(vb.x, vb.y, BsH[kp][nn],     BsL[kp][nn]);
            split2(vb.z, vb.w, BsH[kp + 1][nn], BsL[kp + 1][nn]);
        }
        __syncthreads();

        // ---- fragments ----
        uint32_t aH[2][4], aL[2][4], bH[4][2], bL[4][2];
#pragma unroll
        for (int mt = 0; mt < 2; mt++) {
            int m = wm0 + mt * 16 + gp;
            aH[mt][0] = AsH[m][tg];     aL[mt][0] = AsL[m][tg];
            aH[mt][1] = AsH[m + 8][tg]; aL[mt][1] = AsL[m + 8][tg];
            aH[mt][2] = AsH[m][tg + 4]; aL[mt][2] = AsL[m][tg + 4];
            aH[mt][3] = AsH[m + 8][tg + 4]; aL[mt][3] = AsL[m + 8][tg + 4];
        }
#pragma unroll
        for (int nt = 0; nt < 4; nt++) {
            int n = wn0 + nt * 8 + gp;
            bH[nt][0] = BsH[tg][n];     bL[nt][0] = BsL[tg][n];
            bH[nt][1] = BsH[tg + 4][n]; bL[nt][1] = BsL[tg + 4][n];
        }
        // ---- 3 split terms: hi*hi + hi*lo + lo*hi ----
#pragma unroll
        for (int mt = 0; mt < 2; mt++)
#pragma unroll
            for (int nt = 0; nt < 4; nt++) {
                MMA_BF16(acc[mt][nt], aH[mt], bH[nt]);
                MMA_BF16(acc[mt][nt], aH[mt], bL[nt]);
                MMA_BF16(acc[mt][nt], aL[mt], bH[nt]);
            }
        __syncthreads();
    }

    // Epilogue: c0/c1 at (row, 2*tg), c2/c3 at (row+8, 2*tg)
#pragma unroll
    for (int mt = 0; mt < 2; mt++) {
        long long r = row0 + wm0 + mt * 16 + gp;
#pragma unroll
        for (int nt = 0; nt < 4; nt++) {
            int c = col0 + wn0 + nt * 8 + tg * 2;
            float b0 = bias ? bias[c] : 0.f;
            float b1 = bias ? bias[c + 1] : 0.f;
            float2 lo = make_float2(acc[mt][nt][0] + b0, acc[mt][nt][1] + b1);
            float2 hi = make_float2(acc[mt][nt][2] + b0, acc[mt][nt][3] + b1);
            *(float2*)(C + r * ldc + c) = lo;
            *(float2*)(C + (r + 8) * ldc + c) = hi;
        }
    }
}

// ---------------------------------------------------------------------------
// Softmax over rows of length SEQ. masked: row i uses first i+1 elems.
// ---------------------------------------------------------------------------
__global__ void __launch_bounds__(256) softmax_kernel(float* __restrict__ sc, int masked)
{
    long long base = (long long)blockIdx.x * SEQ;
    int i = blockIdx.x & (SEQ - 1);
    int n = masked ? (i + 1) : SEQ;
    int tid = threadIdx.x;
    __shared__ float red[8];

    float v[4];
    float mx = -1e30f;
#pragma unroll
    for (int j = 0; j < 4; j++) {
        int c = tid + (j << 8);
        v[j] = (c < n) ? sc[base + c] : -1e30f;
        mx = fmaxf(mx, v[j]);
    }
#pragma unroll
    for (int o = 16; o; o >>= 1) mx = fmaxf(mx, __shfl_xor_sync(0xffffffffu, mx, o));
    if ((tid & 31) == 0) red[tid >> 5] = mx;
    __syncthreads();
    mx = red[0];
#pragma unroll
    for (int w = 1; w < 8; w++) mx = fmaxf(mx, red[w]);
    __syncthreads();

    float s = 0.f;
#pragma unroll
    for (int j = 0; j < 4; j++) {
        int c = tid + (j << 8);
        v[j] = (c < n) ? __expf(v[j] - mx) : 0.f;
        s += v[j];
    }
#pragma unroll
    for (int o = 16; o; o >>= 1) s += __shfl_xor_sync(0xffffffffu, s, o);
    if ((tid & 31) == 0) red[tid >> 5] = s;
    __syncthreads();
    s = 0.f;
#pragma unroll
    for (int w = 0; w < 8; w++) s += red[w];
    float inv = 1.f / s;
#pragma unroll
    for (int j = 0; j < 4; j++) {
        int c = tid + (j << 8);
        sc[base + c] = v[j] * inv;
    }
}

// ---------------------------------------------------------------------------
// y = LayerNorm(a + r). One block (256 thr) per row of 512.
// ---------------------------------------------------------------------------
__global__ void __launch_bounds__(256) ln_kernel(
    const float* __restrict__ a, const float* __restrict__ r,
    const float* __restrict__ g, const float* __restrict__ b,
    float* __restrict__ y)
{
    long long base = (long long)blockIdx.x * HIDX;
    int tid = threadIdx.x;
    __shared__ float red[8];

    float z0 = a[base + tid] + r[base + tid];
    float z1 = a[base + tid + 256] + r[base + tid + 256];
    float s = z0 + z1;
#pragma unroll
    for (int o = 16; o; o >>= 1) s += __shfl_xor_sync(0xffffffffu, s, o);
    if ((tid & 31) == 0) red[tid >> 5] = s;
    __syncthreads();
    s = 0.f;
#pragma unroll
    for (int w = 0; w < 8; w++) s += red[w];
    float m = s * (1.f / HIDX);
    float d0 = z0 - m, d1 = z1 - m;
    float qs = d0 * d0 + d1 * d1;
    __syncthreads();
#pragma unroll
    for (int o = 16; o; o >>= 1) qs += __shfl_xor_sync(0xffffffffu, qs, o);
    if ((tid & 31) == 0) red[tid >> 5] = qs;
    __syncthreads();
    qs = 0.f;
#pragma unroll
    for (int w = 0; w < 8; w++) qs += red[w];
    float inv = rsqrtf(qs * (1.f / HIDX) + EPSV);
    y[base + tid]       = g[tid] * d0 * inv + b[tid];
    y[base + tid + 256] = g[tid + 256] * d1 * inv + b[tid + 256];
}

// ---------------------------------------------------------------------------
// Gate: softmax(x@gw+gb) over E=8, pick 2nd-largest (faithful TOPK-1 bug).
// ---------------------------------------------------------------------------
__global__ void __launch_bounds__(256) gate_kernel(
    const float* __restrict__ x, const float* __restrict__ gw, const float* __restrict__ gb)
{
    int tok = (blockIdx.x << 3) + (threadIdx.x >> 5);
    int lane = threadIdx.x & 31;
    const float* xr = x + (size_t)tok * HIDX;
    float acc[8] = {0, 0, 0, 0, 0, 0, 0, 0};
    for (int j = lane; j < HIDX; j += 32) {
        float xv = xr[j];
        float4 a0 = *(const float4*)(gw + j * 8);
        float4 a1 = *(const float4*)(gw + j * 8 + 4);
        acc[0] += xv * a0.x; acc[1] += xv * a0.y; acc[2] += xv * a0.z; acc[3] += xv * a0.w;
        acc[4] += xv * a1.x; acc[5] += xv * a1.y; acc[6] += xv * a1.z; acc[7] += xv * a1.w;
    }
#pragma unroll
    for (int e = 0; e < 8; e++)
#pragma unroll
        for (int o = 16; o; o >>= 1) acc[e] += __shfl_xor_sync(0xffffffffu, acc[e], o);
    if (lane == 0) {
        float mx = -1e30f;
#pragma unroll
        for (int e = 0; e < 8; e++) { acc[e] += gb[e]; mx = fmaxf(mx, acc[e]); }
        float p[8];
#pragma unroll
        for (int e = 0; e < 8; e++) p[e] = __expf(acc[e] - mx);
        float v1 = -1.f, v2 = -1.f; int i1 = 0, i2 = 0;
#pragma unroll
        for (int e = 0; e < 8; e++) {
            if (p[e] > v1)      { v2 = v1; i2 = i1; v1 = p[e]; i1 = e; }
            else if (p[e] > v2) { v2 = p[e]; i2 = e; }
        }
        g_sel[tok] = i2;
        g_wsel[tok] = v2 / (v1 + v2);
    }
}

// ---------------------------------------------------------------------------
// Build tile-aligned per-expert permutation + tile descriptors (1 block).
// ---------------------------------------------------------------------------
__global__ void __launch_bounds__(256) moe_setup()
{
    __shared__ int cnt[8], cursor[8];
    int tid = threadIdx.x;
    if (tid < 8) cnt[tid] = 0;
    for (int i = tid; i < MAXROWS; i += 256) g_perm[i] = -1;
    __syncthreads();
    for (int i = tid; i < TOK; i += 256) atomicAdd(&cnt[g_sel[i]], 1);
    __syncthreads();
    if (tid == 0) {
        int base = 0, t = 0;
        for (int e = 0; e < 8; e++) {
            cursor[e] = base;
            int tiles = (cnt[e] + 63) >> 6;
            for (int j = 0; j < tiles; j++) g_texp[t++] = e;
            base += tiles << 6;
        }
        for (; t < MAXT; t++) g_texp[t] = -1;
    }
    __syncthreads();
    for (int i = tid; i < TOK; i += 256) {
        int e = g_sel[i];
        int p = atomicAdd(&cursor[e], 1);
        g_perm[p] = i;
    }
}

// ---------------------------------------------------------------------------
// MoE GEMM1: h = relu(x[perm] @ w1[e] + b1[e]), 64x64x16 tiles, 4x4/thread.
// ---------------------------------------------------------------------------
__global__ void __launch_bounds__(256) moe_gemm1(
    const float* __restrict__ x, const float* __restrict__ w1, const float* __restrict__ b1)
{
    int t = blockIdx.y;
    int e = g_texp[t];
    if (e < 0) return;
    const float* B = w1 + (size_t)e * HIDX * FFN;
    const float* bias = b1 + (size_t)e * FFN;
    int col0 = blockIdx.x << 6;
    __shared__ float As[16][68];
    __shared__ float Bs[16][68];
    __shared__ int rows[64];
    int tid = threadIdx.x;
    if (tid < 64) rows[tid] = g_perm[(t << 6) + tid];
    __syncthreads();
    int tx = tid & 15, ty = tid >> 4;
    float acc[4][4] = {};
    for (int k0 = 0; k0 < HIDX; k0 += 16) {
        int mm = tid >> 2, k4 = (tid & 3) << 2;
        int r = rows[mm];
        float4 va = make_float4(0.f, 0.f, 0.f, 0.f);
        if (r >= 0) va = *(const float4*)(x + (size_t)r * HIDX + k0 + k4);
        As[k4 + 0][mm] = va.x; As[k4 + 1][mm] = va.y;
        As[k4 + 2][mm] = va.z; As[k4 + 3][mm] = va.w;
        int kk = tid >> 4, nn = (tid & 15) << 2;
        float4 vb = *(const float4*)(B + (size_t)(k0 + kk) * FFN + col0 + nn);
        Bs[kk][nn] = vb.x; Bs[kk][nn + 1] = vb.y;
        Bs[kk][nn + 2] = vb.z; Bs[kk][nn + 3] = vb.w;
        __syncthreads();
#pragma unroll
        for (int kk2 = 0; kk2 < 16; kk2++) {
            float av[4], bv[4];
#pragma unroll
            for (int i = 0; i < 4; i++) av[i] = As[kk2][ty * 4 + i];
#pragma unroll
            for (int j = 0; j < 4; j++) bv[j] = Bs[kk2][tx * 4 + j];
#pragma unroll
            for (int i = 0; i < 4; i++)
#pragma unroll
                for (int j = 0; j < 4; j++)
                    acc[i][j] = fmaf(av[i], bv[j], acc[i][j]);
        }
        __syncthreads();
    }
#pragma unroll
    for (int i = 0; i < 4; i++) {
#pragma unroll
        for (int j = 0; j < 4; j++) {
            int c = col0 + tx * 4 + j;
            float vv = acc[i][j] + bias[c];
            vv = fmaxf(vv, 0.f);
            g_h[(size_t)((t << 6) + ty * 4 + i) * FFN + c] = vv;
        }
    }
}

// ---------------------------------------------------------------------------
// MoE GEMM2: y[tok] = (h @ w2[e] + b2[e]) * wsel[tok], scattered by perm.
// ---------------------------------------------------------------------------
__global__ void __launch_bounds__(256) moe_gemm2(
    const float* __restrict__ w2, const float* __restrict__ b2)
{
    int t = blockIdx.y;
    int e = g_texp[t];
    if (e < 0) return;
    const float* B = w2 + (size_t)e * FFN * HIDX;
    const float* bias = b2 + (size_t)e * HIDX;
    int col0 = blockIdx.x << 6;
    __shared__ float As[16][68];
    __shared__ float Bs[16][68];
    __shared__ int rows[64];
    int tid = threadIdx.x;
    if (tid < 64) rows[tid] = g_perm[(t << 6) + tid];
    __syncthreads();
    int tx = tid & 15, ty = tid >> 4;
    float acc[4][4] = {};
    for (int k0 = 0; k0 < FFN; k0 += 16) {
        int mm = tid >> 2, k4 = (tid & 3) << 2;
        float4 va = *(const float4*)(&g_h[(size_t)((t << 6) + mm) * FFN + k0 + k4]);
        As[k4 + 0][mm] = va.x; As[k4 + 1][mm] = va.y;
        As[k4 + 2][mm] = va.z; As[k4 + 3][mm] = va.w;
        int kk = tid >> 4, nn = (tid & 15) << 2;
        float4 vb = *(const float4*)(B + (size_t)(k0 + kk) * HIDX + col0 + nn);
        Bs[kk][nn] = vb.x; Bs[kk][nn + 1] = vb.y;
        Bs[kk][nn + 2] = vb.z; Bs[kk][nn + 3] = vb.w;
        __syncthreads();
#pragma unroll
        for (int kk2 = 0; kk2 < 16; kk2++) {
            float av[4], bv[4];
#pragma unroll
            for (int i = 0; i < 4; i++) av[i] = As[kk2][ty * 4 + i];
#pragma unroll
            for (int j = 0; j < 4; j++) bv[j] = Bs[kk2][tx * 4 + j];
#pragma unroll
            for (int i = 0; i < 4; i++)
#pragma unroll
                for (int j = 0; j < 4; j++)
                    acc[i][j] = fmaf(av[i], bv[j], acc[i][j]);
        }
        __syncthreads();
    }
#pragma unroll
    for (int i = 0; i < 4; i++) {
        int r = rows[ty * 4 + i];
        if (r < 0) continue;
        float ws = g_wsel[r];
#pragma unroll
        for (int j = 0; j < 4; j++) {
            int c = col0 + tx * 4 + j;
            g_y[(size_t)r * HIDX + c] = (acc[i][j] + bias[c]) * ws;
        }
    }
}

__global__ void __launch_bounds__(256) copy_kernel(float* __restrict__ dst,
                                                   const float* __restrict__ src, int n)
{
    int i = blockIdx.x * 256 + threadIdx.x;
    if (i < n) dst[i] = src[i];
}

// ---------------------------------------------------------------------------
extern "C" void kernel_launch(void* const* d_in, const int* in_sizes, int n_in,
                              void* d_out, int out_size)
{
    const float* x_in = (const float*)d_in[0];
    const float* enc  = (const float*)d_in[1];
    const float* wq = (const float*)d_in[2];
    const float* bq = (const float*)d_in[3];
    const float* wk = (const float*)d_in[4];
    const float* bk = (const float*)d_in[5];
    const float* wv = (const float*)d_in[6];
    const float* bv = (const float*)d_in[7];
    const float* wo = (const float*)d_in[8];
    const float* bo = (const float*)d_in[9];
    const float* gw = (const float*)d_in[10];
    const float* gb = (const float*)d_in[11];
    const float* w1 = (const float*)d_in[12];
    const float* b1 = (const float*)d_in[13];
    const float* w2 = (const float*)d_in[14];
    const float* b2 = (const float*)d_in[15];
    const float* lng = (const float*)d_in[16];
    const float* lnb = (const float*)d_in[17];
    float* out = (float*)d_out;

    float *q, *k, *v, *sc, *o2, *t1, *xb, *yb;
    cudaGetSymbolAddress((void**)&q,  g_q);
    cudaGetSymbolAddress((void**)&k,  g_k);
    cudaGetSymbolAddress((void**)&v,  g_v);
    cudaGetSymbolAddress((void**)&sc, g_sc);
    cudaGetSymbolAddress((void**)&o2, g_o2);
    cudaGetSymbolAddress((void**)&t1, g_t1);
    cudaGetSymbolAddress((void**)&xb, g_x);
    cudaGetSymbolAddress((void**)&yb, g_y);

    copy_kernel<<<TOK * HIDX / 256, 256>>>(xb, x_in, TOK * HIDX);

    for (int l = 0; l < NL; l++) {
        for (int a = 0; a < 2; a++) {
            const float* qin = a ? enc : xb;   // cross-attn: Q,K from encoder
            const float* kin = qin;
            const float* vin = xb;             // V always from current x (faithful)
            size_t wOff = (size_t)(l * 2 + a) * HIDX * HH;
            int msk = (a == 0);

            dim3 gProj(HH / 64, TOK / 128, 1);
            gemm_kernel<<<gProj, 256>>>(qin, HIDX, 0, 0, wq + wOff, HH, 0, 0,
                                        q, HH, 0, 0, bq + (size_t)(l * 2 + a) * HH,
                                        HIDX, 0, 0, 0);
            gemm_kernel<<<gProj, 256>>>(kin, HIDX, 0, 0, wk + wOff, HH, 0, 0,
                                        k, HH, 0, 0, bk + (size_t)(l * 2 + a) * HH,
                                        HIDX, 0, 0, 0);
            gemm_kernel<<<gProj, 256>>>(vin, HIDX, 0, 0, wv + wOff, HH, 0, 0,
                                        v, HH, 0, 0, bv + (size_t)(l * 2 + a) * HH,
                                        HIDX, 0, 0, 0);
            // scores = Q @ K^T per (b,h): NT, batch 32
            gemm_kernel<<<dim3(SEQ / 64, SEQ / 128, 32), 256>>>(
                q, HIDX, 4194304LL, 524288LL,
                k, HIDX, 4194304LL, 524288LL,
                sc, SEQ, 8388608LL, 1048576LL,
                nullptr, HIDX, 1, msk, 0);
            softmax_kernel<<<NB * NH * SEQ, 256>>>(sc, msk);
            // O2[b, s, h*512+d] = sum_j attn[b,h,s,j] * v[b,h,j,d]
            gemm_kernel<<<dim3(HIDX / 64, SEQ / 128, 32), 256>>>(
                sc, SEQ, 8388608LL, 1048576LL,
                v, HIDX, 4194304LL, 524288LL,
                o2, HH, 4194304LL, 512LL,
                nullptr, SEQ, 0, 0, msk);
            gemm_kernel<<<dim3(HIDX / 64, TOK / 128, 1), 256>>>(
                o2, HH, 0, 0, wo + wOff, HIDX, 0, 0,
                t1, HIDX, 0, 0, bo + (size_t)(l * 2 + a) * HIDX,
                HH, 0, 0, 0);
            ln_kernel<<<TOK, 256>>>(t1, xb, lng + (size_t)(l * 3 + a) * HIDX,
                                    lnb + (size_t)(l * 3 + a) * HIDX, xb);
        }
        gate_kernel<<<TOK / 8, 256>>>(xb, gw + (size_t)l * HIDX * NE, gb + (size_t)l * NE);
        moe_setup<<<1, 256>>>();
        moe_gemm1<<<dim3(FFN / 64, MAXT), 256>>>(xb, w1 + (size_t)l * NE * HIDX * FFN,
                                                 b1 + (size_t)l * NE * FFN);
        moe_gemm2<<<dim3(HIDX / 64, MAXT), 256>>>(w2 + (size_t)l * NE * FFN * HIDX,
                                                  b2 + (size_t)l * NE * HIDX);
        ln_kernel<<<TOK, 256>>>(yb, xb, lng + (size_t)(l * 3 + 2) * HIDX,
                                lnb + (size_t)(l * 3 + 2) * HIDX, xb);
    }
    copy_kernel<<<TOK * HIDX / 256, 256>>>(out, xb, TOK * HIDX);
}